// round 11
// baseline (speedup 1.0000x reference)
#include <cuda_runtime.h>
#include <cuda_bf16.h>
#include <math.h>
#include <stdint.h>

#define S_LEN 2048
#define HID   4096
#define NH    32
#define NKV   8
#define HD    128
#define KVDIM 1024
#define KDIM  4096
#define KS    (KDIM / 16)   // 256 k16 units
#define KS2   (KDIM / 32)   // 128 k32 stages

// ---------------- scratch ----------------
__device__ __align__(16) __nv_bfloat16 g_qh[S_LEN * HID],  g_ql[S_LEN * HID];
__device__ __align__(16) __nv_bfloat16 g_kh[S_LEN * KVDIM], g_kl[S_LEN * KVDIM];
__device__ __align__(16) __nv_bfloat16 g_vh[S_LEN * KVDIM], g_vl[S_LEN * KVDIM];
__device__ float4 g_pa_hs[(S_LEN / 128) * KS * 512];
__device__ float4 g_pa_at[(S_LEN / 128) * KS * 512];
__device__ float4 g_pb_wq[(HID / 128) * KS * 512];
__device__ float4 g_pb_wk[(KVDIM / 128) * KS * 512];
__device__ float4 g_pb_wv[(KVDIM / 128) * KS * 512];
__device__ float4 g_pb_wo[(HID / 128) * KS * 512];

// ---------------- helpers ----------------
__device__ __forceinline__ uint32_t smem_u32(const void* p) {
    uint32_t a;
    asm("{ .reg .u64 t; cvta.to.shared.u64 t, %1; cvt.u32.u64 %0, t; }" : "=r"(a) : "l"(p));
    return a;
}
__device__ __forceinline__ void cp_async16s(uint32_t s, const void* g) {
    asm volatile("cp.async.cg.shared.global [%0], [%1], 16;\n" :: "r"(s), "l"(g));
}
__device__ __forceinline__ float f2tf_f(float x) {
    uint32_t u;
    asm("cvt.rna.tf32.f32 %0, %1;" : "=r"(u) : "f"(x));
    return __uint_as_float(u);
}
__device__ __forceinline__ void mma_tf32(float c[4], const uint32_t a[4],
                                         uint32_t b0, uint32_t b1) {
    asm volatile(
        "mma.sync.aligned.m16n8k8.row.col.f32.tf32.tf32.f32 "
        "{%0,%1,%2,%3},{%4,%5,%6,%7},{%8,%9},{%0,%1,%2,%3};"
        : "+f"(c[0]), "+f"(c[1]), "+f"(c[2]), "+f"(c[3])
        : "r"(a[0]), "r"(a[1]), "r"(a[2]), "r"(a[3]), "r"(b0), "r"(b1));
}

// ---------------------------------------------------------------------------
// Unified pack: tf32-round + fragment-pack for all 5 tensors, smem-staged.
// Block handles one (tensor, rb, ks) 128x16 f32 tile.
//   load: fully coalesced float4 row chunks
//   smem: stride 36 floats -> pack-phase reads are bank-conflict-free (4g+t)
//   store: packed float4, fully coalesced
// amode=1 (A-operand order) / 0 (B-operand order); values identical to the
// old pack_a/pack_b kernels.
// ---------------------------------------------------------------------------
#define SEG_HS 16
#define SEG_WQ 48
#define SEG_WK 56
#define SEG_WV 64
#define SEG_WO 96
#define PACK_BLOCKS (SEG_WO * 256)

__global__ __launch_bounds__(256) void pack_all(
    const float* __restrict__ hs, const float* __restrict__ Wq,
    const float* __restrict__ Wk, const float* __restrict__ Wv,
    const float* __restrict__ Wo,
    float4* __restrict__ Phs, float4* __restrict__ Pwq,
    float4* __restrict__ Pwk, float4* __restrict__ Pwv,
    float4* __restrict__ Pwo) {
    __shared__ float S[128 * 36];
    const int tid  = threadIdx.x;
    const int tile = blockIdx.x;
    const int ks   = tile & 255;
    const int seg  = tile >> 8;

    const float* X;  float4* P;  int rb, amode;
    if (seg < SEG_HS)      { X = hs; P = Phs; rb = seg;          amode = 1; }
    else if (seg < SEG_WQ) { X = Wq; P = Pwq; rb = seg - SEG_HS; amode = 0; }
    else if (seg < SEG_WK) { X = Wk; P = Pwk; rb = seg - SEG_WQ; amode = 0; }
    else if (seg < SEG_WV) { X = Wv; P = Pwv; rb = seg - SEG_WK; amode = 0; }
    else                   { X = Wo; P = Pwo; rb = seg - SEG_WV; amode = 0; }

    const float* Xb = X + (size_t)rb * 128 * KDIM + ks * 16;
    #pragma unroll
    for (int j = 0; j < 2; ++j) {
        int li = tid + j * 256;
        int row = li >> 2, c4 = (li & 3) << 2;
        float4 v = *(const float4*)(Xb + (size_t)row * KDIM + c4);
        *(float4*)&S[row * 36 + c4] = v;
    }
    __syncthreads();

    float4* Pb = P + (((size_t)rb << 17) | ((size_t)ks << 9));
    #pragma unroll
    for (int j = 0; j < 2; ++j) {
        int oo = tid + j * 256;
        int lane = oo & 31, mb = (oo >> 5) & 7, kk = oo >> 8;
        int g = lane >> 2, t = lane & 3;
        int r = mb * 16 + g, c = kk * 8 + t;
        float a0 = S[r * 36 + c];
        float a1 = S[(r + 8) * 36 + c];
        float a2 = S[r * 36 + c + 4];
        float a3 = S[(r + 8) * 36 + c + 4];
        float4 pv;
        if (amode) pv = make_float4(f2tf_f(a0), f2tf_f(a1), f2tf_f(a2), f2tf_f(a3));
        else       pv = make_float4(f2tf_f(a0), f2tf_f(a2), f2tf_f(a1), f2tf_f(a3));
        Pb[oo] = pv;
    }
}

// ---------------------------------------------------------------------------
// Fragment-packed TF32 GEMM: CTA 128x256, warp 64x64, k=32/stage, 3-stage ring.
// split!=0 => write bf16 hi/lo split outputs (for q/k/v); else f32.
// ---------------------------------------------------------------------------
#define STG_F4  3072
#define STG_BY  (STG_F4 * 16)
#define PK2_SMEM (3 * STG_BY)

__global__ __launch_bounds__(256, 1)
void gemm_pk2(const float4* __restrict__ PA,
              const float4* __restrict__ B0, int nt0, float* C0f,
              __nv_bfloat16* C0h, __nv_bfloat16* C0l, int ld0,
              const float4* __restrict__ B1, int nt1, float* C1f,
              __nv_bfloat16* C1h, __nv_bfloat16* C1l, int ld1,
              const float4* __restrict__ B2, int nt2, float* C2f,
              __nv_bfloat16* C2h, __nv_bfloat16* C2l, int ld2,
              int split) {
    extern __shared__ float4 sm4[];
    const int tid = threadIdx.x, warp = tid >> 5, lane = tid & 31;
    const int g = lane >> 2, t = lane & 3;
    const int wm = warp & 1;
    const int wn = warp >> 1;
    const uint32_t sb = smem_u32(sm4);

    int nt = blockIdx.x;
    const float4* PB;  float* Cf;  __nv_bfloat16 *Ch, *Cl;  int ld;
    if (nt < nt0)            { PB = B0; Cf = C0f; Ch = C0h; Cl = C0l; ld = ld0; }
    else if (nt < nt0 + nt1) { nt -= nt0;       PB = B1; Cf = C1f; Ch = C1h; Cl = C1l; ld = ld1; }
    else                     { nt -= nt0 + nt1; PB = B2; Cf = C2f; Ch = C2h; Cl = C2l; ld = ld2; }

    const size_t abase  = (size_t)blockIdx.y * KS * 512;
    const size_t bbase0 = (size_t)(2 * nt)     * KS * 512;
    const size_t bbase1 = (size_t)(2 * nt + 1) * KS * 512;

    float c[4][8][4];
    #pragma unroll
    for (int mt = 0; mt < 4; mt++)
        #pragma unroll
        for (int ntb = 0; ntb < 8; ntb++)
            #pragma unroll
            for (int i = 0; i < 4; i++) c[mt][ntb][i] = 0.f;

    #define STAGE2(s_)                                                          \
        do {                                                                    \
            const uint32_t db = sb + (uint32_t)((s_) % 3) * STG_BY;             \
            const size_t koff = (size_t)(s_) * 1024;                            \
            _Pragma("unroll")                                                   \
            for (int i_ = 0; i_ < 12; ++i_) {                                   \
                int cix = tid + i_ * 256;                                       \
                const float4* src;                                              \
                if (cix < 1024)       src = PA + abase  + koff + cix;           \
                else if (cix < 2048)  src = PB + bbase0 + koff + (cix - 1024);  \
                else                  src = PB + bbase1 + koff + (cix - 2048);  \
                cp_async16s(db + (uint32_t)cix * 16u, src);                     \
            }                                                                   \
            asm volatile("cp.async.commit_group;\n" ::);                        \
        } while (0)

    STAGE2(0);
    STAGE2(1);

    const int bblk = wn >> 1;
    const int bnp0 = (wn & 1) * 4;

    for (int s = 0; s < KS2; ++s) {
        if (s + 1 < KS2) asm volatile("cp.async.wait_group 1;\n" ::);
        else             asm volatile("cp.async.wait_group 0;\n" ::);
        __syncthreads();

        if (s + 2 < KS2) STAGE2(s + 2);

        const float4* As4 = sm4 + (s % 3) * STG_F4;
        const float4* Bs4 = As4 + 1024 + bblk * 1024;
        #pragma unroll
        for (int kk2 = 0; kk2 < 4; ++kk2) {
            const int koffs = (kk2 >> 1) * 512 + (kk2 & 1) * 256;
            float4 av[4], bv[4];
            #pragma unroll
            for (int mt = 0; mt < 4; ++mt)
                av[mt] = As4[koffs + (wm * 4 + mt) * 32 + lane];
            #pragma unroll
            for (int np = 0; np < 4; ++np)
                bv[np] = Bs4[koffs + (bnp0 + np) * 32 + lane];
            #pragma unroll
            for (int mt = 0; mt < 4; ++mt) {
                uint32_t a[4] = { __float_as_uint(av[mt].x), __float_as_uint(av[mt].y),
                                  __float_as_uint(av[mt].z), __float_as_uint(av[mt].w) };
                #pragma unroll
                for (int ntb = 0; ntb < 8; ++ntb) {
                    const float4& b = bv[ntb >> 1];
                    uint32_t b0 = (ntb & 1) ? __float_as_uint(b.z) : __float_as_uint(b.x);
                    uint32_t b1 = (ntb & 1) ? __float_as_uint(b.w) : __float_as_uint(b.y);
                    mma_tf32(c[mt][ntb], a, b0, b1);
                }
            }
        }
    }

    const int bm = blockIdx.y * 128, bn = nt * 256;
    #pragma unroll
    for (int mt = 0; mt < 4; ++mt) {
        #pragma unroll
        for (int ntb = 0; ntb < 8; ++ntb) {
            const int row = bm + wm * 64 + mt * 16 + g;
            const int col = bn + wn * 64 + ntb * 8 + 2 * t;
            if (!split) {
                *(float2*)&Cf[(size_t)row * ld + col]       = make_float2(c[mt][ntb][0], c[mt][ntb][1]);
                *(float2*)&Cf[(size_t)(row + 8) * ld + col] = make_float2(c[mt][ntb][2], c[mt][ntb][3]);
            } else {
                size_t e0 = (size_t)row * ld + col;
                size_t e1 = (size_t)(row + 8) * ld + col;
                __nv_bfloat162 h0 = __floats2bfloat162_rn(c[mt][ntb][0], c[mt][ntb][1]);
                __nv_bfloat162 h1 = __floats2bfloat162_rn(c[mt][ntb][2], c[mt][ntb][3]);
                __nv_bfloat162 l0 = __floats2bfloat162_rn(c[mt][ntb][0] - __low2float(h0),
                                                          c[mt][ntb][1] - __high2float(h0));
                __nv_bfloat162 l1 = __floats2bfloat162_rn(c[mt][ntb][2] - __low2float(h1),
                                                          c[mt][ntb][3] - __high2float(h1));
                *(__nv_bfloat162*)&Ch[e0] = h0;  *(__nv_bfloat162*)&Cl[e0] = l0;
                *(__nv_bfloat162*)&Ch[e1] = h1;  *(__nv_bfloat162*)&Cl[e1] = l1;
            }
        }
    }
}

// ---------------------------------------------------------------------------
// Attention: ABQ=64, ABK=32, 4 warps, 2 CTAs/SM. Q FRAGMENTS HOISTED TO
// REGISTERS (loaded once, no per-tile Q ldmatrix). Packed-A epilogue.
// ---------------------------------------------------------------------------
#define ABQ  64
#define ABK  32
#define APAD 136
#define KVBUF (4 * ABK * APAD)
#define ASMEM2 ((2 * ABQ * APAD + 2 * KVBUF) * 2)

__device__ __forceinline__ void ldsm_x4(uint32_t r[4], const void* p) {
    uint32_t a = smem_u32(p);
    asm volatile("ldmatrix.sync.aligned.m8n8.x4.shared.b16 {%0,%1,%2,%3}, [%4];"
                 : "=r"(r[0]), "=r"(r[1]), "=r"(r[2]), "=r"(r[3]) : "r"(a));
}
__device__ __forceinline__ void ldsm_x4_t(uint32_t r[4], const void* p) {
    uint32_t a = smem_u32(p);
    asm volatile("ldmatrix.sync.aligned.m8n8.x4.trans.shared.b16 {%0,%1,%2,%3}, [%4];"
                 : "=r"(r[0]), "=r"(r[1]), "=r"(r[2]), "=r"(r[3]) : "r"(a));
}
__device__ __forceinline__ void mma_bf16(float c[4], const uint32_t a[4],
                                         uint32_t b0, uint32_t b1) {
    asm volatile(
        "mma.sync.aligned.m16n8k16.row.col.f32.bf16.bf16.f32 "
        "{%0,%1,%2,%3},{%4,%5,%6,%7},{%8,%9},{%0,%1,%2,%3};"
        : "+f"(c[0]), "+f"(c[1]), "+f"(c[2]), "+f"(c[3])
        : "r"(a[0]), "r"(a[1]), "r"(a[2]), "r"(a[3]), "r"(b0), "r"(b1));
}

__device__ __forceinline__ int nextv(int kb, int kb_max, int q0, int n_init, int n_local) {
    while (kb <= kb_max) {
        int k0 = kb * ABK;
        if (!(k0 >= n_init && (q0 - (k0 + ABK - 1)) >= n_local)) break;
        kb++;
    }
    return kb;
}

__global__ __launch_bounds__(128, 2) void attn_cp(
    const __nv_bfloat16* __restrict__ Qhg, const __nv_bfloat16* __restrict__ Qlg,
    const __nv_bfloat16* __restrict__ Khg, const __nv_bfloat16* __restrict__ Klg,
    const __nv_bfloat16* __restrict__ Vhg, const __nv_bfloat16* __restrict__ Vlg,
    float4* __restrict__ PAout,
    const int* __restrict__ n_init_p, const int* __restrict__ n_local_p) {

    extern __shared__ __nv_bfloat16 smb[];
    __nv_bfloat16* Qh  = smb;
    __nv_bfloat16* Ql  = Qh + ABQ * APAD;
    __nv_bfloat16* KV0 = Ql + ABQ * APAD;

    const int h   = blockIdx.y;
    const int q0  = blockIdx.x * ABQ;
    const int hkv = h >> 2;
    const int n_init  = *n_init_p;
    const int n_local = *n_local_p;

    const int tid  = threadIdx.x;
    const int warp = tid >> 5;
    const int lane = tid & 31;
    const int g    = lane >> 2;
    const int t    = lane & 3;
    const int grp  = lane >> 3;

    const int kb_max = (q0 + ABQ - 1) / ABK;

    #define STAGE_KV(bufp, k0_)                                                  \
        do {                                                                     \
            const __nv_bfloat16* gsrc_[4] = { Khg, Klg, Vhg, Vlg };              \
            _Pragma("unroll")                                                    \
            for (int it_ = 0; it_ < 16; ++it_) {                                 \
                int idx = tid + it_ * 128;                                       \
                int ts_ = idx >> 9, rc_ = idx & 511;                             \
                int row_ = rc_ >> 4, ch_ = rc_ & 15;                             \
                const __nv_bfloat16* src = gsrc_[ts_] +                          \
                    (size_t)((k0_) + row_) * KVDIM + hkv * HD + ch_ * 8;         \
                __nv_bfloat16* dst = (bufp) + ts_ * (ABK * APAD)                 \
                    + row_ * APAD + ch_ * 8;                                     \
                cp_async16s(smem_u32(dst), src);                                 \
            }                                                                    \
        } while (0)

    // prologue: Q + first KV tile (group 0), second KV tile (group 1)
    {
        #pragma unroll
        for (int it = 0; it < 16; ++it) {
            int idx = tid + it * 128;
            int ts = idx >> 10, rc = idx & 1023;
            int row = rc >> 4, ch = rc & 15;
            const __nv_bfloat16* src = (ts ? Qlg : Qhg) +
                (size_t)(q0 + row) * HID + h * HD + ch * 8;
            __nv_bfloat16* dst = (ts ? Ql : Qh) + row * APAD + ch * 8;
            cp_async16s(smem_u32(dst), src);
        }
    }
    int cur = nextv(0, kb_max, q0, n_init, n_local);
    STAGE_KV(KV0, cur * ABK);
    asm volatile("cp.async.commit_group;\n" ::);
    int nxt = nextv(cur + 1, kb_max, q0, n_init, n_local);
    if (nxt <= kb_max) STAGE_KV(KV0 + KVBUF, nxt * ABK);
    asm volatile("cp.async.commit_group;\n" ::);

    // ---- hoist Q fragments into registers (Q is in group 0) ----
    uint32_t qfh[8][4], qfl[8][4];
    asm volatile("cp.async.wait_group 1;\n" ::);
    __syncthreads();
    #pragma unroll
    for (int kk = 0; kk < 8; ++kk) {
        const int aoff = (warp * 16 + (lane & 15)) * APAD + kk * 16 + (lane >> 4) * 8;
        ldsm_x4(qfh[kk], Qh + aoff);
        ldsm_x4(qfl[kk], Ql + aoff);
    }

    float o[16][4];
    float m_i[2] = {-1e30f, -1e30f};
    float l_i[2] = {0.f, 0.f};
    #pragma unroll
    for (int nb = 0; nb < 16; nb++)
        #pragma unroll
        for (int j = 0; j < 4; j++) o[nb][j] = 0.f;

    const int   row0  = q0 + warp * 16 + g;
    const float scale = 0.08838834764831845f;
    int buf = 0;

    while (cur <= kb_max) {
        const int k0 = cur * ABK;
        asm volatile("cp.async.wait_group 1;\n" ::);
        __syncthreads();

        __nv_bfloat16* Kh = KV0 + buf * KVBUF;
        __nv_bfloat16* Kl = Kh + ABK * APAD;
        __nv_bfloat16* Vh = Kl + ABK * APAD;
        __nv_bfloat16* Vl = Vh + ABK * APAD;

        // ---- S = Q @ K^T (3-term split), Q from registers ----
        float sc[4][4];
        #pragma unroll
        for (int nb = 0; nb < 4; nb++)
            #pragma unroll
            for (int j = 0; j < 4; j++) sc[nb][j] = 0.f;

        #pragma unroll
        for (int kk = 0; kk < 8; ++kk) {
            #pragma unroll
            for (int nbp = 0; nbp < 2; ++nbp) {
                uint32_t kb_h[4], kb_l[4];
                const int boff = (nbp * 16 + (grp >> 1) * 8 + (lane & 7)) * APAD
                               + kk * 16 + (grp & 1) * 8;
                ldsm_x4(kb_h, Kh + boff);
                ldsm_x4(kb_l, Kl + boff);
                mma_bf16(sc[2 * nbp],     qfh[kk], kb_h[0], kb_h[1]);
                mma_bf16(sc[2 * nbp],     qfh[kk], kb_l[0], kb_l[1]);
                mma_bf16(sc[2 * nbp],     qfl[kk], kb_h[0], kb_h[1]);
                mma_bf16(sc[2 * nbp + 1], qfh[kk], kb_h[2], kb_h[3]);
                mma_bf16(sc[2 * nbp + 1], qfh[kk], kb_l[2], kb_l[3]);
                mma_bf16(sc[2 * nbp + 1], qfl[kk], kb_h[2], kb_h[3]);
            }
        }

        // ---- mask + online softmax ----
        float tm0 = -1e30f, tm1 = -1e30f;
        #pragma unroll
        for (int nb = 0; nb < 4; ++nb) {
            int cb = k0 + nb * 8 + 2 * t;
            #pragma unroll
            for (int j = 0; j < 2; ++j) {
                int cc = cb + j;
                bool ok0 = (cc <= row0)     && (cc < n_init || row0 - cc < n_local);
                bool ok1 = (cc <= row0 + 8) && (cc < n_init || row0 + 8 - cc < n_local);
                sc[nb][j]     = ok0 ? sc[nb][j] * scale     : -1e30f;
                sc[nb][2 + j] = ok1 ? sc[nb][2 + j] * scale : -1e30f;
                tm0 = fmaxf(tm0, sc[nb][j]);
                tm1 = fmaxf(tm1, sc[nb][2 + j]);
            }
        }
        tm0 = fmaxf(tm0, __shfl_xor_sync(0xffffffffu, tm0, 1));
        tm0 = fmaxf(tm0, __shfl_xor_sync(0xffffffffu, tm0, 2));
        tm1 = fmaxf(tm1, __shfl_xor_sync(0xffffffffu, tm1, 1));
        tm1 = fmaxf(tm1, __shfl_xor_sync(0xffffffffu, tm1, 2));

        float mn0 = fmaxf(m_i[0], tm0), mn1 = fmaxf(m_i[1], tm1);
        float al0 = __expf(m_i[0] - mn0), al1 = __expf(m_i[1] - mn1);
        float rs0 = 0.f, rs1 = 0.f;
        #pragma unroll
        for (int nb = 0; nb < 4; ++nb) {
            #pragma unroll
            for (int j = 0; j < 2; ++j) {
                float p0 = __expf(sc[nb][j] - mn0);
                float p1 = __expf(sc[nb][2 + j] - mn1);
                sc[nb][j] = p0;  sc[nb][2 + j] = p1;
                rs0 += p0;  rs1 += p1;
            }
        }
        rs0 += __shfl_xor_sync(0xffffffffu, rs0, 1);
        rs0 += __shfl_xor_sync(0xffffffffu, rs0, 2);
        rs1 += __shfl_xor_sync(0xffffffffu, rs1, 1);
        rs1 += __shfl_xor_sync(0xffffffffu, rs1, 2);
        l_i[0] = l_i[0] * al0 + rs0;  m_i[0] = mn0;
        l_i[1] = l_i[1] * al1 + rs1;  m_i[1] = mn1;
        #pragma unroll
        for (int nb = 0; nb < 16; ++nb) {
            o[nb][0] *= al0;  o[nb][1] *= al0;
            o[nb][2] *= al1;  o[nb][3] *= al1;
        }

        // ---- pack P fragments (hi/lo) from registers ----
        uint32_t ph[4][2], pl[4][2];
        #pragma unroll
        for (int nb = 0; nb < 4; ++nb) {
            __nv_bfloat162 h0 = __floats2bfloat162_rn(sc[nb][0], sc[nb][1]);
            __nv_bfloat162 h1 = __floats2bfloat162_rn(sc[nb][2], sc[nb][3]);
            float r0 = sc[nb][0] - __low2float(h0), r1 = sc[nb][1] - __high2float(h0);
            float r2 = sc[nb][2] - __low2float(h1), r3 = sc[nb][3] - __high2float(h1);
            __nv_bfloat162 q0b = __floats2bfloat162_rn(r0, r1);
            __nv_bfloat162 q1b = __floats2bfloat162_rn(r2, r3);
            ph[nb][0] = *(uint32_t*)&h0;  ph[nb][1] = *(uint32_t*)&h1;
            pl[nb][0] = *(uint32_t*)&q0b; pl[nb][1] = *(uint32_t*)&q1b;
        }

        // ---- O += P @ V (3-term split) ----
        #pragma unroll
        for (int ks = 0; ks < 2; ++ks) {
            uint32_t aH[4] = { ph[2 * ks][0], ph[2 * ks][1],
                               ph[2 * ks + 1][0], ph[2 * ks + 1][1] };
            uint32_t aL[4] = { pl[2 * ks][0], pl[2 * ks][1],
                               pl[2 * ks + 1][0], pl[2 * ks + 1][1] };
            #pragma unroll
            for (int np = 0; np < 8; ++np) {
                uint32_t vh[4], vl[4];
                const int voff = (ks * 16 + (grp & 1) * 8 + (lane & 7)) * APAD
                               + (np * 2 + (grp >> 1)) * 8;
                ldsm_x4_t(vh, Vh + voff);
                ldsm_x4_t(vl, Vl + voff);
                mma_bf16(o[2 * np],     aH, vh[0], vh[1]);
                mma_bf16(o[2 * np],     aH, vl[0], vl[1]);
                mma_bf16(o[2 * np],     aL, vh[0], vh[1]);
                mma_bf16(o[2 * np + 1], aH, vh[2], vh[3]);
                mma_bf16(o[2 * np + 1], aH, vl[2], vl[3]);
                mma_bf16(o[2 * np + 1], aL, vh[2], vh[3]);
            }
        }

        __syncthreads();
        int nn = (nxt <= kb_max) ? nextv(nxt + 1, kb_max, q0, n_init, n_local)
                                 : kb_max + 1;
        if (nn <= kb_max) STAGE_KV(KV0 + buf * KVBUF, nn * ABK);
        asm volatile("cp.async.commit_group;\n" ::);
        cur = nxt;  nxt = nn;  buf ^= 1;
    }

    // ---- fused epilogue: normalize + butterfly to packed-A fragment layout ----
    {
        float inv0 = 1.f / l_i[0], inv1 = 1.f / l_i[1];
        #pragma unroll
        for (int nb = 0; nb < 16; ++nb) {
            o[nb][0] *= inv0;  o[nb][1] *= inv0;
            o[nb][2] *= inv1;  o[nb][3] *= inv1;
        }
        const int pt   = lane & 3;
        const int srcA = (lane & ~3) | (pt >> 1);
        const int srcB = srcA + 2;
        const bool odd = pt & 1;
        const size_t rb = (size_t)(blockIdx.x >> 1);
        const size_t mb = (size_t)((blockIdx.x & 1) * 4 + warp);
        const size_t base = (rb << 17) | (mb << 5) | (size_t)lane;
        #pragma unroll
        for (int nb = 0; nb < 16; ++nb) {
            float s0 = __shfl_sync(0xffffffffu, o[nb][0], srcA);
            float s1 = __shfl_sync(0xffffffffu, o[nb][1], srcA);
            float s2 = __shfl_sync(0xffffffffu, o[nb][2], srcA);
            float s3 = __shfl_sync(0xffffffffu, o[nb][3], srcA);
            float u0 = __shfl_sync(0xffffffffu, o[nb][0], srcB);
            float u1 = __shfl_sync(0xffffffffu, o[nb][1], srcB);
            float u2 = __shfl_sync(0xffffffffu, o[nb][2], srcB);
            float u3 = __shfl_sync(0xffffffffu, o[nb][3], srcB);
            float4 pv;
            pv.x = f2tf_f(odd ? s1 : s0);
            pv.y = f2tf_f(odd ? s3 : s2);
            pv.z = f2tf_f(odd ? u1 : u0);
            pv.w = f2tf_f(odd ? u3 : u2);
            const size_t ksg = (size_t)(h * 8 + (nb >> 1));
            PAout[base + ((size_t)(nb & 1) << 8) + (ksg << 9)] = pv;
        }
    }
}

// ---------------------------------------------------------------------------
extern "C" void kernel_launch(void* const* d_in, const int* in_sizes, int n_in,
                              void* d_out, int out_size) {
    const float* hs = (const float*)d_in[0];
    const float* Wq = (const float*)d_in[1];
    const float* Wk = (const float*)d_in[2];
    const float* Wv = (const float*)d_in[3];
    const float* Wo = (const float*)d_in[4];
    const int* n_init  = (const int*)d_in[5];
    const int* n_local = (const int*)d_in[6];
    float* out = (float*)d_out;

    __nv_bfloat16 *qh, *ql, *kh, *kl, *vh, *vl;
    cudaGetSymbolAddress((void**)&qh, g_qh);  cudaGetSymbolAddress((void**)&ql, g_ql);
    cudaGetSymbolAddress((void**)&kh, g_kh);  cudaGetSymbolAddress((void**)&kl, g_kl);
    cudaGetSymbolAddress((void**)&vh, g_vh);  cudaGetSymbolAddress((void**)&vl, g_vl);
    float4 *pa_hs, *pa_at, *pb_wq, *pb_wk, *pb_wv, *pb_wo;
    cudaGetSymbolAddress((void**)&pa_hs, g_pa_hs);
    cudaGetSymbolAddress((void**)&pa_at, g_pa_at);
    cudaGetSymbolAddress((void**)&pb_wq, g_pb_wq);
    cudaGetSymbolAddress((void**)&pb_wk, g_pb_wk);
    cudaGetSymbolAddress((void**)&pb_wv, g_pb_wv);
    cudaGetSymbolAddress((void**)&pb_wo, g_pb_wo);

    static int attr_set = 0;
    if (!attr_set) {
        cudaFuncSetAttribute(attn_cp,  cudaFuncAttributeMaxDynamicSharedMemorySize, ASMEM2);
        cudaFuncSetAttribute(gemm_pk2, cudaFuncAttributeMaxDynamicSharedMemorySize, PK2_SMEM);
        attr_set = 1;
    }

    // One unified, coalesced pack pass for all five tensors
    pack_all<<<PACK_BLOCKS, 256>>>(hs, Wq, Wk, Wv, Wo,
                                   pa_hs, pb_wq, pb_wk, pb_wv, pb_wo);

    // Fused QKV projection with split-bf16 outputs
    gemm_pk2<<<dim3(24, S_LEN / 128), 256, PK2_SMEM>>>(
        pa_hs,
        pb_wq, 16, nullptr, qh, ql, HID,
        pb_wk, 4,  nullptr, kh, kl, KVDIM,
        pb_wv, 4,  nullptr, vh, vl, KVDIM,
        1);

    // Attention (64-row q-blocks, 2 CTAs/SM, Q in registers) -> packed pa_at
    attn_cp<<<dim3(S_LEN / ABQ, NH), 128, ASMEM2>>>(qh, ql, kh, kl, vh, vl,
                                                    pa_at, n_init, n_local);

    // Output projection (f32 out) straight from packed attention output
    gemm_pk2<<<dim3(16, S_LEN / 128), 256, PK2_SMEM>>>(
        pa_at,
        pb_wo, 16, out, nullptr, nullptr, HID,
        pb_wo, 0,  out, nullptr, nullptr, HID,
        pb_wo, 0,  out, nullptr, nullptr, HID,
        0);
}

// round 12
// speedup vs baseline: 1.0394x; 1.0394x over previous
#include <cuda_runtime.h>
#include <cuda_bf16.h>
#include <math.h>
#include <stdint.h>

#define S_LEN 2048
#define HID   4096
#define NH    32
#define NKV   8
#define HD    128
#define KVDIM 1024
#define KDIM  4096
#define KS    (KDIM / 16)   // 256 k16 units
#define NS64  (KDIM / 64)   // 64 k64 stages

// ---------------- scratch ----------------
__device__ __align__(16) __nv_bfloat16 g_qh[S_LEN * HID],  g_ql[S_LEN * HID];
__device__ __align__(16) __nv_bfloat16 g_kh[S_LEN * KVDIM], g_kl[S_LEN * KVDIM];
__device__ __align__(16) __nv_bfloat16 g_vh[S_LEN * KVDIM], g_vl[S_LEN * KVDIM];
__device__ float4 g_pa_hs[(S_LEN / 128) * KS * 512];
__device__ float4 g_pa_at[(S_LEN / 128) * KS * 512];
__device__ float4 g_pb_wq[(HID / 128) * KS * 512];
__device__ float4 g_pb_wk[(KVDIM / 128) * KS * 512];
__device__ float4 g_pb_wv[(KVDIM / 128) * KS * 512];
__device__ float4 g_pb_wo[(HID / 128) * KS * 512];

// ---------------- helpers ----------------
__device__ __forceinline__ uint32_t smem_u32(const void* p) {
    uint32_t a;
    asm("{ .reg .u64 t; cvta.to.shared.u64 t, %1; cvt.u32.u64 %0, t; }" : "=r"(a) : "l"(p));
    return a;
}
__device__ __forceinline__ void cp_async16s(uint32_t s, const void* g) {
    asm volatile("cp.async.cg.shared.global [%0], [%1], 16;\n" :: "r"(s), "l"(g));
}
__device__ __forceinline__ float f2tf_f(float x) {
    uint32_t u;
    asm("cvt.rna.tf32.f32 %0, %1;" : "=r"(u) : "f"(x));
    return __uint_as_float(u);
}
__device__ __forceinline__ void mma_tf32(float c[4], const uint32_t a[4],
                                         uint32_t b0, uint32_t b1) {
    asm volatile(
        "mma.sync.aligned.m16n8k8.row.col.f32.tf32.tf32.f32 "
        "{%0,%1,%2,%3},{%4,%5,%6,%7},{%8,%9},{%0,%1,%2,%3};"
        : "+f"(c[0]), "+f"(c[1]), "+f"(c[2]), "+f"(c[3])
        : "r"(a[0]), "r"(a[1]), "r"(a[2]), "r"(a[3]), "r"(b0), "r"(b1));
}

// ---------------------------------------------------------------------------
// Unified pack: tf32-round + fragment-pack for all 5 tensors, smem-staged.
// ---------------------------------------------------------------------------
#define SEG_HS 16
#define SEG_WQ 48
#define SEG_WK 56
#define SEG_WV 64
#define SEG_WO 96
#define PACK_BLOCKS (SEG_WO * 256)

__global__ __launch_bounds__(256) void pack_all(
    const float* __restrict__ hs, const float* __restrict__ Wq,
    const float* __restrict__ Wk, const float* __restrict__ Wv,
    const float* __restrict__ Wo,
    float4* __restrict__ Phs, float4* __restrict__ Pwq,
    float4* __restrict__ Pwk, float4* __restrict__ Pwv,
    float4* __restrict__ Pwo) {
    __shared__ float S[128 * 36];
    const int tid  = threadIdx.x;
    const int tile = blockIdx.x;
    const int ks   = tile & 255;
    const int seg  = tile >> 8;

    const float* X;  float4* P;  int rb, amode;
    if (seg < SEG_HS)      { X = hs; P = Phs; rb = seg;          amode = 1; }
    else if (seg < SEG_WQ) { X = Wq; P = Pwq; rb = seg - SEG_HS; amode = 0; }
    else if (seg < SEG_WK) { X = Wk; P = Pwk; rb = seg - SEG_WQ; amode = 0; }
    else if (seg < SEG_WV) { X = Wv; P = Pwv; rb = seg - SEG_WK; amode = 0; }
    else                   { X = Wo; P = Pwo; rb = seg - SEG_WV; amode = 0; }

    const float* Xb = X + (size_t)rb * 128 * KDIM + ks * 16;
    #pragma unroll
    for (int j = 0; j < 2; ++j) {
        int li = tid + j * 256;
        int row = li >> 2, c4 = (li & 3) << 2;
        float4 v = *(const float4*)(Xb + (size_t)row * KDIM + c4);
        *(float4*)&S[row * 36 + c4] = v;
    }
    __syncthreads();

    float4* Pb = P + (((size_t)rb << 17) | ((size_t)ks << 9));
    #pragma unroll
    for (int j = 0; j < 2; ++j) {
        int oo = tid + j * 256;
        int lane = oo & 31, mb = (oo >> 5) & 7, kk = oo >> 8;
        int g = lane >> 2, t = lane & 3;
        int r = mb * 16 + g, c = kk * 8 + t;
        float a0 = S[r * 36 + c];
        float a1 = S[(r + 8) * 36 + c];
        float a2 = S[r * 36 + c + 4];
        float a3 = S[(r + 8) * 36 + c + 4];
        float4 pv;
        if (amode) pv = make_float4(f2tf_f(a0), f2tf_f(a1), f2tf_f(a2), f2tf_f(a3));
        else       pv = make_float4(f2tf_f(a0), f2tf_f(a2), f2tf_f(a1), f2tf_f(a3));
        Pb[oo] = pv;
    }
}

// ---------------------------------------------------------------------------
// Fragment-packed TF32 GEMM v3: CTA 128x256, warp 64x64, k=64/stage,
// 2-stage ring (192 KB). Same accumulation order as v2 (bit-identical).
// split!=0 => bf16 hi/lo split outputs; else f32.
// ---------------------------------------------------------------------------
#define STG_F4  6144                 // A 2048 + B0 2048 + B1 2048 float4
#define STG_BY  (STG_F4 * 16)        // 98304 bytes
#define PK2_SMEM (2 * STG_BY)        // 196608 bytes

__global__ __launch_bounds__(256, 1)
void gemm_pk2(const float4* __restrict__ PA,
              const float4* __restrict__ B0, int nt0, float* C0f,
              __nv_bfloat16* C0h, __nv_bfloat16* C0l, int ld0,
              const float4* __restrict__ B1, int nt1, float* C1f,
              __nv_bfloat16* C1h, __nv_bfloat16* C1l, int ld1,
              const float4* __restrict__ B2, int nt2, float* C2f,
              __nv_bfloat16* C2h, __nv_bfloat16* C2l, int ld2,
              int split) {
    extern __shared__ float4 sm4[];
    const int tid = threadIdx.x, warp = tid >> 5, lane = tid & 31;
    const int g = lane >> 2, t = lane & 3;
    const int wm = warp & 1;
    const int wn = warp >> 1;
    const uint32_t sb = smem_u32(sm4);

    int nt = blockIdx.x;
    const float4* PB;  float* Cf;  __nv_bfloat16 *Ch, *Cl;  int ld;
    if (nt < nt0)            { PB = B0; Cf = C0f; Ch = C0h; Cl = C0l; ld = ld0; }
    else if (nt < nt0 + nt1) { nt -= nt0;       PB = B1; Cf = C1f; Ch = C1h; Cl = C1l; ld = ld1; }
    else                     { nt -= nt0 + nt1; PB = B2; Cf = C2f; Ch = C2h; Cl = C2l; ld = ld2; }

    const size_t abase  = (size_t)blockIdx.y * KS * 512;
    const size_t bbase0 = (size_t)(2 * nt)     * KS * 512;
    const size_t bbase1 = (size_t)(2 * nt + 1) * KS * 512;

    float c[4][8][4];
    #pragma unroll
    for (int mt = 0; mt < 4; mt++)
        #pragma unroll
        for (int ntb = 0; ntb < 8; ntb++)
            #pragma unroll
            for (int i = 0; i < 4; i++) c[mt][ntb][i] = 0.f;

    // stage s (k64 = 2048 f4 per operand block) into buffer s%2
    #define STAGE3(s_)                                                          \
        do {                                                                    \
            const uint32_t db = sb + (uint32_t)((s_) & 1) * STG_BY;             \
            const size_t koff = (size_t)(s_) * 2048;                            \
            _Pragma("unroll")                                                   \
            for (int i_ = 0; i_ < 24; ++i_) {                                   \
                int cix = tid + i_ * 256;                                       \
                const float4* src;                                              \
                if (cix < 2048)       src = PA + abase  + koff + cix;           \
                else if (cix < 4096)  src = PB + bbase0 + koff + (cix - 2048);  \
                else                  src = PB + bbase1 + koff + (cix - 4096);  \
                cp_async16s(db + (uint32_t)cix * 16u, src);                     \
            }                                                                   \
            asm volatile("cp.async.commit_group;\n" ::);                        \
        } while (0)

    STAGE3(0);
    STAGE3(1);

    const int bblk = wn >> 1;
    const int bnp0 = (wn & 1) * 4;

    for (int s = 0; s < NS64; ++s) {
        if (s + 1 < NS64) asm volatile("cp.async.wait_group 1;\n" ::);
        else              asm volatile("cp.async.wait_group 0;\n" ::);
        __syncthreads();

        const float4* As4 = sm4 + (s & 1) * STG_F4;
        const float4* Bs4 = As4 + 2048 + bblk * 2048;
        #pragma unroll
        for (int kk2 = 0; kk2 < 8; ++kk2) {     // 8 x k8 within k64 stage
            const int koffs = (kk2 >> 1) * 512 + (kk2 & 1) * 256;
            float4 av[4], bv[4];
            #pragma unroll
            for (int mt = 0; mt < 4; ++mt)
                av[mt] = As4[koffs + (wm * 4 + mt) * 32 + lane];
            #pragma unroll
            for (int np = 0; np < 4; ++np)
                bv[np] = Bs4[koffs + (bnp0 + np) * 32 + lane];
            #pragma unroll
            for (int mt = 0; mt < 4; ++mt) {
                uint32_t a[4] = { __float_as_uint(av[mt].x), __float_as_uint(av[mt].y),
                                  __float_as_uint(av[mt].z), __float_as_uint(av[mt].w) };
                #pragma unroll
                for (int ntb = 0; ntb < 8; ++ntb) {
                    const float4& b = bv[ntb >> 1];
                    uint32_t b0 = (ntb & 1) ? __float_as_uint(b.z) : __float_as_uint(b.x);
                    uint32_t b1 = (ntb & 1) ? __float_as_uint(b.w) : __float_as_uint(b.y);
                    mma_tf32(c[mt][ntb], a, b0, b1);
                }
            }
        }

        if (s + 2 < NS64) {
            __syncthreads();       // all warps done reading buffer s&1
            STAGE3(s + 2);
        }
    }

    const int bm = blockIdx.y * 128, bn = nt * 256;
    #pragma unroll
    for (int mt = 0; mt < 4; ++mt) {
        #pragma unroll
        for (int ntb = 0; ntb < 8; ++ntb) {
            const int row = bm + wm * 64 + mt * 16 + g;
            const int col = bn + wn * 64 + ntb * 8 + 2 * t;
            if (!split) {
                *(float2*)&Cf[(size_t)row * ld + col]       = make_float2(c[mt][ntb][0], c[mt][ntb][1]);
                *(float2*)&Cf[(size_t)(row + 8) * ld + col] = make_float2(c[mt][ntb][2], c[mt][ntb][3]);
            } else {
                size_t e0 = (size_t)row * ld + col;
                size_t e1 = (size_t)(row + 8) * ld + col;
                __nv_bfloat162 h0 = __floats2bfloat162_rn(c[mt][ntb][0], c[mt][ntb][1]);
                __nv_bfloat162 h1 = __floats2bfloat162_rn(c[mt][ntb][2], c[mt][ntb][3]);
                __nv_bfloat162 l0 = __floats2bfloat162_rn(c[mt][ntb][0] - __low2float(h0),
                                                          c[mt][ntb][1] - __high2float(h0));
                __nv_bfloat162 l1 = __floats2bfloat162_rn(c[mt][ntb][2] - __low2float(h1),
                                                          c[mt][ntb][3] - __high2float(h1));
                *(__nv_bfloat162*)&Ch[e0] = h0;  *(__nv_bfloat162*)&Cl[e0] = l0;
                *(__nv_bfloat162*)&Ch[e1] = h1;  *(__nv_bfloat162*)&Cl[e1] = l1;
            }
        }
    }
}

// ---------------------------------------------------------------------------
// Attention: ABQ=64, ABK=32, 4 warps, 2 CTAs/SM, Q fragments hoisted,
// double-buffered KV ring, packed-A fragment epilogue. (round-11 kernel)
// ---------------------------------------------------------------------------
#define ABQ  64
#define ABK  32
#define APAD 136
#define KVBUF (4 * ABK * APAD)
#define ASMEM2 ((2 * ABQ * APAD + 2 * KVBUF) * 2)

__device__ __forceinline__ void ldsm_x4(uint32_t r[4], const void* p) {
    uint32_t a = smem_u32(p);
    asm volatile("ldmatrix.sync.aligned.m8n8.x4.shared.b16 {%0,%1,%2,%3}, [%4];"
                 : "=r"(r[0]), "=r"(r[1]), "=r"(r[2]), "=r"(r[3]) : "r"(a));
}
__device__ __forceinline__ void ldsm_x4_t(uint32_t r[4], const void* p) {
    uint32_t a = smem_u32(p);
    asm volatile("ldmatrix.sync.aligned.m8n8.x4.trans.shared.b16 {%0,%1,%2,%3}, [%4];"
                 : "=r"(r[0]), "=r"(r[1]), "=r"(r[2]), "=r"(r[3]) : "r"(a));
}
__device__ __forceinline__ void mma_bf16(float c[4], const uint32_t a[4],
                                         uint32_t b0, uint32_t b1) {
    asm volatile(
        "mma.sync.aligned.m16n8k16.row.col.f32.bf16.bf16.f32 "
        "{%0,%1,%2,%3},{%4,%5,%6,%7},{%8,%9},{%0,%1,%2,%3};"
        : "+f"(c[0]), "+f"(c[1]), "+f"(c[2]), "+f"(c[3])
        : "r"(a[0]), "r"(a[1]), "r"(a[2]), "r"(a[3]), "r"(b0), "r"(b1));
}

__device__ __forceinline__ int nextv(int kb, int kb_max, int q0, int n_init, int n_local) {
    while (kb <= kb_max) {
        int k0 = kb * ABK;
        if (!(k0 >= n_init && (q0 - (k0 + ABK - 1)) >= n_local)) break;
        kb++;
    }
    return kb;
}

__global__ __launch_bounds__(128, 2) void attn_cp(
    const __nv_bfloat16* __restrict__ Qhg, const __nv_bfloat16* __restrict__ Qlg,
    const __nv_bfloat16* __restrict__ Khg, const __nv_bfloat16* __restrict__ Klg,
    const __nv_bfloat16* __restrict__ Vhg, const __nv_bfloat16* __restrict__ Vlg,
    float4* __restrict__ PAout,
    const int* __restrict__ n_init_p, const int* __restrict__ n_local_p) {

    extern __shared__ __nv_bfloat16 smb[];
    __nv_bfloat16* Qh  = smb;
    __nv_bfloat16* Ql  = Qh + ABQ * APAD;
    __nv_bfloat16* KV0 = Ql + ABQ * APAD;

    const int h   = blockIdx.y;
    const int q0  = blockIdx.x * ABQ;
    const int hkv = h >> 2;
    const int n_init  = *n_init_p;
    const int n_local = *n_local_p;

    const int tid  = threadIdx.x;
    const int warp = tid >> 5;
    const int lane = tid & 31;
    const int g    = lane >> 2;
    const int t    = lane & 3;
    const int grp  = lane >> 3;

    const int kb_max = (q0 + ABQ - 1) / ABK;

    #define STAGE_KV(bufp, k0_)                                                  \
        do {                                                                     \
            const __nv_bfloat16* gsrc_[4] = { Khg, Klg, Vhg, Vlg };              \
            _Pragma("unroll")                                                    \
            for (int it_ = 0; it_ < 16; ++it_) {                                 \
                int idx = tid + it_ * 128;                                       \
                int ts_ = idx >> 9, rc_ = idx & 511;                             \
                int row_ = rc_ >> 4, ch_ = rc_ & 15;                             \
                const __nv_bfloat16* src = gsrc_[ts_] +                          \
                    (size_t)((k0_) + row_) * KVDIM + hkv * HD + ch_ * 8;         \
                __nv_bfloat16* dst = (bufp) + ts_ * (ABK * APAD)                 \
                    + row_ * APAD + ch_ * 8;                                     \
                cp_async16s(smem_u32(dst), src);                                 \
            }                                                                    \
        } while (0)

    {
        #pragma unroll
        for (int it = 0; it < 16; ++it) {
            int idx = tid + it * 128;
            int ts = idx >> 10, rc = idx & 1023;
            int row = rc >> 4, ch = rc & 15;
            const __nv_bfloat16* src = (ts ? Qlg : Qhg) +
                (size_t)(q0 + row) * HID + h * HD + ch * 8;
            __nv_bfloat16* dst = (ts ? Ql : Qh) + row * APAD + ch * 8;
            cp_async16s(smem_u32(dst), src);
        }
    }
    int cur = nextv(0, kb_max, q0, n_init, n_local);
    STAGE_KV(KV0, cur * ABK);
    asm volatile("cp.async.commit_group;\n" ::);
    int nxt = nextv(cur + 1, kb_max, q0, n_init, n_local);
    if (nxt <= kb_max) STAGE_KV(KV0 + KVBUF, nxt * ABK);
    asm volatile("cp.async.commit_group;\n" ::);

    uint32_t qfh[8][4], qfl[8][4];
    asm volatile("cp.async.wait_group 1;\n" ::);
    __syncthreads();
    #pragma unroll
    for (int kk = 0; kk < 8; ++kk) {
        const int aoff = (warp * 16 + (lane & 15)) * APAD + kk * 16 + (lane >> 4) * 8;
        ldsm_x4(qfh[kk], Qh + aoff);
        ldsm_x4(qfl[kk], Ql + aoff);
    }

    float o[16][4];
    float m_i[2] = {-1e30f, -1e30f};
    float l_i[2] = {0.f, 0.f};
    #pragma unroll
    for (int nb = 0; nb < 16; nb++)
        #pragma unroll
        for (int j = 0; j < 4; j++) o[nb][j] = 0.f;

    const int   row0  = q0 + warp * 16 + g;
    const float scale = 0.08838834764831845f;
    int buf = 0;

    while (cur <= kb_max) {
        const int k0 = cur * ABK;
        asm volatile("cp.async.wait_group 1;\n" ::);
        __syncthreads();

        __nv_bfloat16* Kh = KV0 + buf * KVBUF;
        __nv_bfloat16* Kl = Kh + ABK * APAD;
        __nv_bfloat16* Vh = Kl + ABK * APAD;
        __nv_bfloat16* Vl = Vh + ABK * APAD;

        float sc[4][4];
        #pragma unroll
        for (int nb = 0; nb < 4; nb++)
            #pragma unroll
            for (int j = 0; j < 4; j++) sc[nb][j] = 0.f;

        #pragma unroll
        for (int kk = 0; kk < 8; ++kk) {
            #pragma unroll
            for (int nbp = 0; nbp < 2; ++nbp) {
                uint32_t kb_h[4], kb_l[4];
                const int boff = (nbp * 16 + (grp >> 1) * 8 + (lane & 7)) * APAD
                               + kk * 16 + (grp & 1) * 8;
                ldsm_x4(kb_h, Kh + boff);
                ldsm_x4(kb_l, Kl + boff);
                mma_bf16(sc[2 * nbp],     qfh[kk], kb_h[0], kb_h[1]);
                mma_bf16(sc[2 * nbp],     qfh[kk], kb_l[0], kb_l[1]);
                mma_bf16(sc[2 * nbp],     qfl[kk], kb_h[0], kb_h[1]);
                mma_bf16(sc[2 * nbp + 1], qfh[kk], kb_h[2], kb_h[3]);
                mma_bf16(sc[2 * nbp + 1], qfh[kk], kb_l[2], kb_l[3]);
                mma_bf16(sc[2 * nbp + 1], qfl[kk], kb_h[2], kb_h[3]);
            }
        }

        float tm0 = -1e30f, tm1 = -1e30f;
        #pragma unroll
        for (int nb = 0; nb < 4; ++nb) {
            int cb = k0 + nb * 8 + 2 * t;
            #pragma unroll
            for (int j = 0; j < 2; ++j) {
                int cc = cb + j;
                bool ok0 = (cc <= row0)     && (cc < n_init || row0 - cc < n_local);
                bool ok1 = (cc <= row0 + 8) && (cc < n_init || row0 + 8 - cc < n_local);
                sc[nb][j]     = ok0 ? sc[nb][j] * scale     : -1e30f;
                sc[nb][2 + j] = ok1 ? sc[nb][2 + j] * scale : -1e30f;
                tm0 = fmaxf(tm0, sc[nb][j]);
                tm1 = fmaxf(tm1, sc[nb][2 + j]);
            }
        }
        tm0 = fmaxf(tm0, __shfl_xor_sync(0xffffffffu, tm0, 1));
        tm0 = fmaxf(tm0, __shfl_xor_sync(0xffffffffu, tm0, 2));
        tm1 = fmaxf(tm1, __shfl_xor_sync(0xffffffffu, tm1, 1));
        tm1 = fmaxf(tm1, __shfl_xor_sync(0xffffffffu, tm1, 2));

        float mn0 = fmaxf(m_i[0], tm0), mn1 = fmaxf(m_i[1], tm1);
        float al0 = __expf(m_i[0] - mn0), al1 = __expf(m_i[1] - mn1);
        float rs0 = 0.f, rs1 = 0.f;
        #pragma unroll
        for (int nb = 0; nb < 4; ++nb) {
            #pragma unroll
            for (int j = 0; j < 2; ++j) {
                float p0 = __expf(sc[nb][j] - mn0);
                float p1 = __expf(sc[nb][2 + j] - mn1);
                sc[nb][j] = p0;  sc[nb][2 + j] = p1;
                rs0 += p0;  rs1 += p1;
            }
        }
        rs0 += __shfl_xor_sync(0xffffffffu, rs0, 1);
        rs0 += __shfl_xor_sync(0xffffffffu, rs0, 2);
        rs1 += __shfl_xor_sync(0xffffffffu, rs1, 1);
        rs1 += __shfl_xor_sync(0xffffffffu, rs1, 2);
        l_i[0] = l_i[0] * al0 + rs0;  m_i[0] = mn0;
        l_i[1] = l_i[1] * al1 + rs1;  m_i[1] = mn1;
        #pragma unroll
        for (int nb = 0; nb < 16; ++nb) {
            o[nb][0] *= al0;  o[nb][1] *= al0;
            o[nb][2] *= al1;  o[nb][3] *= al1;
        }

        uint32_t ph[4][2], pl[4][2];
        #pragma unroll
        for (int nb = 0; nb < 4; ++nb) {
            __nv_bfloat162 h0 = __floats2bfloat162_rn(sc[nb][0], sc[nb][1]);
            __nv_bfloat162 h1 = __floats2bfloat162_rn(sc[nb][2], sc[nb][3]);
            float r0 = sc[nb][0] - __low2float(h0), r1 = sc[nb][1] - __high2float(h0);
            float r2 = sc[nb][2] - __low2float(h1), r3 = sc[nb][3] - __high2float(h1);
            __nv_bfloat162 q0b = __floats2bfloat162_rn(r0, r1);
            __nv_bfloat162 q1b = __floats2bfloat162_rn(r2, r3);
            ph[nb][0] = *(uint32_t*)&h0;  ph[nb][1] = *(uint32_t*)&h1;
            pl[nb][0] = *(uint32_t*)&q0b; pl[nb][1] = *(uint32_t*)&q1b;
        }

        #pragma unroll
        for (int ks = 0; ks < 2; ++ks) {
            uint32_t aH[4] = { ph[2 * ks][0], ph[2 * ks][1],
                               ph[2 * ks + 1][0], ph[2 * ks + 1][1] };
            uint32_t aL[4] = { pl[2 * ks][0], pl[2 * ks][1],
                               pl[2 * ks + 1][0], pl[2 * ks + 1][1] };
            #pragma unroll
            for (int np = 0; np < 8; ++np) {
                uint32_t vh[4], vl[4];
                const int voff = (ks * 16 + (grp & 1) * 8 + (lane & 7)) * APAD
                               + (np * 2 + (grp >> 1)) * 8;
                ldsm_x4_t(vh, Vh + voff);
                ldsm_x4_t(vl, Vl + voff);
                mma_bf16(o[2 * np],     aH, vh[0], vh[1]);
                mma_bf16(o[2 * np],     aH, vl[0], vl[1]);
                mma_bf16(o[2 * np],     aL, vh[0], vh[1]);
                mma_bf16(o[2 * np + 1], aH, vh[2], vh[3]);
                mma_bf16(o[2 * np + 1], aH, vl[2], vl[3]);
                mma_bf16(o[2 * np + 1], aL, vh[2], vh[3]);
            }
        }

        __syncthreads();
        int nn = (nxt <= kb_max) ? nextv(nxt + 1, kb_max, q0, n_init, n_local)
                                 : kb_max + 1;
        if (nn <= kb_max) STAGE_KV(KV0 + buf * KVBUF, nn * ABK);
        asm volatile("cp.async.commit_group;\n" ::);
        cur = nxt;  nxt = nn;  buf ^= 1;
    }

    {
        float inv0 = 1.f / l_i[0], inv1 = 1.f / l_i[1];
        #pragma unroll
        for (int nb = 0; nb < 16; ++nb) {
            o[nb][0] *= inv0;  o[nb][1] *= inv0;
            o[nb][2] *= inv1;  o[nb][3] *= inv1;
        }
        const int pt   = lane & 3;
        const int srcA = (lane & ~3) | (pt >> 1);
        const int srcB = srcA + 2;
        const bool odd = pt & 1;
        const size_t rb = (size_t)(blockIdx.x >> 1);
        const size_t mb = (size_t)((blockIdx.x & 1) * 4 + warp);
        const size_t base = (rb << 17) | (mb << 5) | (size_t)lane;
        #pragma unroll
        for (int nb = 0; nb < 16; ++nb) {
            float s0 = __shfl_sync(0xffffffffu, o[nb][0], srcA);
            float s1 = __shfl_sync(0xffffffffu, o[nb][1], srcA);
            float s2 = __shfl_sync(0xffffffffu, o[nb][2], srcA);
            float s3 = __shfl_sync(0xffffffffu, o[nb][3], srcA);
            float u0 = __shfl_sync(0xffffffffu, o[nb][0], srcB);
            float u1 = __shfl_sync(0xffffffffu, o[nb][1], srcB);
            float u2 = __shfl_sync(0xffffffffu, o[nb][2], srcB);
            float u3 = __shfl_sync(0xffffffffu, o[nb][3], srcB);
            float4 pv;
            pv.x = f2tf_f(odd ? s1 : s0);
            pv.y = f2tf_f(odd ? s3 : s2);
            pv.z = f2tf_f(odd ? u1 : u0);
            pv.w = f2tf_f(odd ? u3 : u2);
            const size_t ksg = (size_t)(h * 8 + (nb >> 1));
            PAout[base + ((size_t)(nb & 1) << 8) + (ksg << 9)] = pv;
        }
    }
}

// ---------------------------------------------------------------------------
extern "C" void kernel_launch(void* const* d_in, const int* in_sizes, int n_in,
                              void* d_out, int out_size) {
    const float* hs = (const float*)d_in[0];
    const float* Wq = (const float*)d_in[1];
    const float* Wk = (const float*)d_in[2];
    const float* Wv = (const float*)d_in[3];
    const float* Wo = (const float*)d_in[4];
    const int* n_init  = (const int*)d_in[5];
    const int* n_local = (const int*)d_in[6];
    float* out = (float*)d_out;

    __nv_bfloat16 *qh, *ql, *kh, *kl, *vh, *vl;
    cudaGetSymbolAddress((void**)&qh, g_qh);  cudaGetSymbolAddress((void**)&ql, g_ql);
    cudaGetSymbolAddress((void**)&kh, g_kh);  cudaGetSymbolAddress((void**)&kl, g_kl);
    cudaGetSymbolAddress((void**)&vh, g_vh);  cudaGetSymbolAddress((void**)&vl, g_vl);
    float4 *pa_hs, *pa_at, *pb_wq, *pb_wk, *pb_wv, *pb_wo;
    cudaGetSymbolAddress((void**)&pa_hs, g_pa_hs);
    cudaGetSymbolAddress((void**)&pa_at, g_pa_at);
    cudaGetSymbolAddress((void**)&pb_wq, g_pb_wq);
    cudaGetSymbolAddress((void**)&pb_wk, g_pb_wk);
    cudaGetSymbolAddress((void**)&pb_wv, g_pb_wv);
    cudaGetSymbolAddress((void**)&pb_wo, g_pb_wo);

    static int attr_set = 0;
    if (!attr_set) {
        cudaFuncSetAttribute(attn_cp,  cudaFuncAttributeMaxDynamicSharedMemorySize, ASMEM2);
        cudaFuncSetAttribute(gemm_pk2, cudaFuncAttributeMaxDynamicSharedMemorySize, PK2_SMEM);
        attr_set = 1;
    }

    pack_all<<<PACK_BLOCKS, 256>>>(hs, Wq, Wk, Wv, Wo,
                                   pa_hs, pb_wq, pb_wk, pb_wv, pb_wo);

    gemm_pk2<<<dim3(24, S_LEN / 128), 256, PK2_SMEM>>>(
        pa_hs,
        pb_wq, 16, nullptr, qh, ql, HID,
        pb_wk, 4,  nullptr, kh, kl, KVDIM,
        pb_wv, 4,  nullptr, vh, vl, KVDIM,
        1);

    attn_cp<<<dim3(S_LEN / ABQ, NH), 128, ASMEM2>>>(qh, ql, kh, kl, vh, vl,
                                                    pa_at, n_init, n_local);

    gemm_pk2<<<dim3(16, S_LEN / 128), 256, PK2_SMEM>>>(
        pa_at,
        pb_wo, 16, out, nullptr, nullptr, HID,
        pb_wo, 0,  out, nullptr, nullptr, HID,
        pb_wo, 0,  out, nullptr, nullptr, HID,
        0);
}